// round 9
// baseline (speedup 1.0000x reference)
#include <cuda_runtime.h>
#include <cuda_bf16.h>
#include <cstdint>

// CenterLoss: out = mean_i ||x_i - centers[labels_i]||^2
// (clamp [1e-12,1e12] dropped: per-row dist ~2D~4096, clamp effect <1e-12/B.)
//
// R8: grouped-by-label main kernel (center row in registers, c L2 traffic
// ~eliminated) + ALL prep fused into one single-CTA smem kernel (probe,
// hist, scan, scatter ~3us instead of 4 launches / ~12us) + persistent
// ticket scheduling in the main kernel (no wave tail) + 64-reg budget
// (R7's 42-reg cap likely spilled).

#define THREADS 256
#define PREPT   1024
#define MAXC_G  1024      // grouped path: C <= 1024
#define MAXB_G  16384     // grouped path: B <= 16384 (labels fit in smem)
#define MAXC 8192
#define MAXB (1 << 18)

__device__ int g_labels_are_i64;
__device__ int d_counts[MAXC];
__device__ int d_offs[MAXC];
__device__ int d_cursor[MAXC];
__device__ int d_rowidx[MAXB];
__device__ int d_ticket;

// ---------------- fused prep: probe + init + hist + scan + scatter -------
__global__ void prep_kernel(const unsigned int* __restrict__ labels_words,
                            float* __restrict__ out, int B, int C) {
    extern __shared__ int sh[];            // [B] labels, [C] scan, [C] cursor
    int* slab = sh;
    int* ssc  = sh + B;
    int* scur = ssc + MAXC_G;

    const int t = threadIdx.x;
    __shared__ int nonzero_odd;
    if (t == 0) { nonzero_odd = 0; out[0] = 0.0f; d_ticket = 0; }
    __syncthreads();
    if (t < 256 && labels_words[2 * t + 1] != 0u) atomicOr(&nonzero_odd, 1);
    for (int i = t; i < C; i += PREPT) scur[i] = 0;   // hist counters
    __syncthreads();
    const int is64 = nonzero_odd ? 0 : 1;
    if (t == 0) g_labels_are_i64 = is64;

    // stage labels + histogram
    for (int i = t; i < B; i += PREPT) {
        int lab = (int)labels_words[is64 ? (2 * i) : i];
        slab[i] = lab;
        atomicAdd(&scur[lab], 1);
    }
    __syncthreads();

    // exclusive scan over C (<=1024) counters, Hillis-Steele on 1024 lanes
    int orig = (t < C) ? scur[t] : 0;
    ssc[t] = orig;
    __syncthreads();
    #pragma unroll
    for (int off = 1; off < PREPT; off <<= 1) {
        int v = (t >= off) ? ssc[t - off] : 0;
        __syncthreads();
        ssc[t] += v;
        __syncthreads();
    }
    if (t < C) {
        int e = ssc[t] - orig;             // exclusive prefix
        d_offs[t]   = e;
        d_counts[t] = orig;
        scur[t] = e;                       // cursor
    }
    __syncthreads();

    // scatter row indices
    for (int i = t; i < B; i += PREPT) {
        int p = atomicAdd(&scur[slab[i]], 1);
        d_rowidx[p] = i;
    }
}

// ---------------- main grouped kernel (persistent + ticket) --------------
// Work item g in [0, 2C): label j = g>>1, half h = g&1 -> bucket rows
// h, h+2, h+4, ... Center row lives in registers (2 float4/thread).
__global__ __launch_bounds__(THREADS, 4)
void center_loss_grouped(const float4* __restrict__ x4,
                         const float4* __restrict__ c4,
                         float* __restrict__ out,
                         int vpr, int nitems, float inv_B) {
    const int t = threadIdx.x;
    __shared__ int sh_g;

    float a0 = 0.f, a1 = 0.f, a2 = 0.f, a3 = 0.f;

    for (;;) {
        if (t == 0) sh_g = atomicAdd(&d_ticket, 1);
        __syncthreads();
        const int g = sh_g;
        __syncthreads();
        if (g >= nitems) break;

        const int j   = g >> 1;
        const int h   = g & 1;
        const int cnt = d_counts[j];
        const int off = d_offs[j];
        if (h >= cnt && h != 0) continue;  // empty half
        if (cnt == 0) continue;

        const float4* __restrict__ cr = c4 + (size_t)j * vpr;
        const float4 c0 = __ldg(cr + t);
        const float4 c1 = __ldg(cr + 256 + t);

        int i = h;
        for (; i + 2 < cnt; i += 4) {
            int r0 = __ldg(&d_rowidx[off + i]);
            int r1 = __ldg(&d_rowidx[off + i + 2]);
            const float4* xa = x4 + (size_t)r0 * vpr;
            const float4* xb = x4 + (size_t)r1 * vpr;
            float4 xa0 = __ldcs(xa + t);
            float4 xa1 = __ldcs(xa + 256 + t);
            float4 xb0 = __ldcs(xb + t);
            float4 xb1 = __ldcs(xb + 256 + t);
            float d;
            d = xa0.x - c0.x; a0 = fmaf(d, d, a0);
            d = xa0.y - c0.y; a1 = fmaf(d, d, a1);
            d = xa0.z - c0.z; a2 = fmaf(d, d, a2);
            d = xa0.w - c0.w; a3 = fmaf(d, d, a3);
            d = xa1.x - c1.x; a0 = fmaf(d, d, a0);
            d = xa1.y - c1.y; a1 = fmaf(d, d, a1);
            d = xa1.z - c1.z; a2 = fmaf(d, d, a2);
            d = xa1.w - c1.w; a3 = fmaf(d, d, a3);
            d = xb0.x - c0.x; a0 = fmaf(d, d, a0);
            d = xb0.y - c0.y; a1 = fmaf(d, d, a1);
            d = xb0.z - c0.z; a2 = fmaf(d, d, a2);
            d = xb0.w - c0.w; a3 = fmaf(d, d, a3);
            d = xb1.x - c1.x; a0 = fmaf(d, d, a0);
            d = xb1.y - c1.y; a1 = fmaf(d, d, a1);
            d = xb1.z - c1.z; a2 = fmaf(d, d, a2);
            d = xb1.w - c1.w; a3 = fmaf(d, d, a3);
        }
        for (; i < cnt; i += 2) {
            int r0 = __ldg(&d_rowidx[off + i]);
            const float4* xa = x4 + (size_t)r0 * vpr;
            float4 xa0 = __ldcs(xa + t);
            float4 xa1 = __ldcs(xa + 256 + t);
            float d;
            d = xa0.x - c0.x; a0 = fmaf(d, d, a0);
            d = xa0.y - c0.y; a1 = fmaf(d, d, a1);
            d = xa0.z - c0.z; a2 = fmaf(d, d, a2);
            d = xa0.w - c0.w; a3 = fmaf(d, d, a3);
            d = xa1.x - c1.x; a0 = fmaf(d, d, a0);
            d = xa1.y - c1.y; a1 = fmaf(d, d, a1);
            d = xa1.z - c1.z; a2 = fmaf(d, d, a2);
            d = xa1.w - c1.w; a3 = fmaf(d, d, a3);
        }
    }

    float s = (a0 + a1) + (a2 + a3);
    #pragma unroll
    for (int o = 16; o; o >>= 1)
        s += __shfl_xor_sync(0xffffffffu, s, o);
    __shared__ float bsum[THREADS / 32];
    if ((t & 31) == 0) bsum[t >> 5] = s;
    __syncthreads();
    if (t == 0) {
        float tt = 0.f;
        #pragma unroll
        for (int w = 0; w < THREADS / 32; w++) tt += bsum[w];
        if (tt != 0.f) atomicAdd(out, tt * inv_B);
    }
}

// ---------------- fallback path (R5) -------------------------------------
__global__ void probe_and_init(const unsigned int* __restrict__ labels_words,
                               float* __restrict__ out) {
    __shared__ int nonzero_odd;
    if (threadIdx.x == 0) { nonzero_odd = 0; out[0] = 0.0f; }
    __syncthreads();
    if (labels_words[2 * threadIdx.x + 1] != 0u) atomicOr(&nonzero_odd, 1);
    __syncthreads();
    if (threadIdx.x == 0) g_labels_are_i64 = nonzero_odd ? 0 : 1;
}

__global__ __launch_bounds__(THREADS, 5)
void center_loss_q(const float4* __restrict__ x4,
                   const int* __restrict__ lab32,
                   const float4* __restrict__ c4,
                   float* __restrict__ out,
                   int nunits, int vpr, int vq, float inv_B) {
    const int lane   = threadIdx.x & 31;
    const int warp   = blockIdx.x * (THREADS / 32) + (threadIdx.x >> 5);
    const int nwarps = gridDim.x * (THREADS / 32);
    const int lsh    = g_labels_are_i64;
    float a0 = 0.f, a1 = 0.f, a2 = 0.f, a3 = 0.f;
    for (int u = warp; u < nunits; u += nwarps) {
        const int row = u >> 2, q = u & 3;
        const int lab = lab32[row << lsh];
        const float4* xp = x4 + (size_t)row * vpr + q * vq + lane;
        const float4* cp = c4 + (size_t)lab * vpr + q * vq + lane;
        #pragma unroll
        for (int k = 0; k < 4; k++) {
            if (q * vq + lane + 32 * k >= vpr) break;
            float4 xv = __ldcs(xp + 32 * k);
            float4 cv = __ldg(cp + 32 * k);
            float d0 = xv.x - cv.x, d1 = xv.y - cv.y;
            float d2 = xv.z - cv.z, d3 = xv.w - cv.w;
            a0 = fmaf(d0, d0, a0); a1 = fmaf(d1, d1, a1);
            a2 = fmaf(d2, d2, a2); a3 = fmaf(d3, d3, a3);
        }
    }
    float s = (a0 + a1) + (a2 + a3);
    #pragma unroll
    for (int o = 16; o; o >>= 1) s += __shfl_xor_sync(0xffffffffu, s, o);
    __shared__ float bsum[THREADS / 32];
    if (lane == 0) bsum[threadIdx.x >> 5] = s;
    __syncthreads();
    if (threadIdx.x == 0) {
        float t = 0.f;
        #pragma unroll
        for (int w = 0; w < THREADS / 32; w++) t += bsum[w];
        atomicAdd(out, t * inv_B);
    }
}

extern "C" void kernel_launch(void* const* d_in, const int* in_sizes, int n_in,
                              void* d_out, int out_size) {
    const float* x       = (const float*)d_in[0];
    const void*  labels  = d_in[1];
    const float* centers = (const float*)d_in[2];
    float*       out     = (float*)d_out;

    const int B   = in_sizes[1];
    const int D   = in_sizes[0] / B;
    const int C   = in_sizes[2] / D;
    const int vpr = D >> 2;
    const float inv_B = 1.0f / (float)B;

    if (D == 2048 && C <= MAXC_G && B <= MAXB_G && B >= 512) {
        const int prep_smem = (B + 2 * MAXC_G) * (int)sizeof(int);
        cudaFuncSetAttribute(prep_kernel,
                             cudaFuncAttributeMaxDynamicSharedMemorySize,
                             prep_smem);
        prep_kernel<<<1, PREPT, prep_smem>>>((const unsigned int*)labels,
                                             out, B, C);
        center_loss_grouped<<<148 * 4, THREADS>>>((const float4*)x,
                                                  (const float4*)centers,
                                                  out, vpr, 2 * C, inv_B);
    } else {
        const int vq = vpr >> 2;
        probe_and_init<<<1, 256>>>((const unsigned int*)labels, out);
        center_loss_q<<<148 * 5, THREADS>>>((const float4*)x, (const int*)labels,
                                            (const float4*)centers, out,
                                            B * 4, vpr, vq, inv_B);
    }
}